// round 16
// baseline (speedup 1.0000x reference)
#include <cuda_runtime.h>

#define L_NODES 30000
#define JDIM 64
#define NFEAT 16
#define NPAIRS (L_NODES / 2)   // 15000 two-node groups

// Scratch (allocation-free): per-node tables.
__device__ float g_hXWt[L_NODES * JDIM];
__device__ float g_hXWb[L_NODES * JDIM];

typedef unsigned long long u64;

// ---- packed f32x2 helpers (sm_100+) ----------------------------------------
__device__ __forceinline__ u64 pack2(float lo, float hi) {
    u64 r; asm("mov.b64 %0, {%1, %2};" : "=l"(r) : "f"(lo), "f"(hi)); return r;
}
__device__ __forceinline__ void ffma2(u64& d, u64 a, u64 b) {
    asm("fma.rn.f32x2 %0, %1, %2, %0;" : "+l"(d) : "l"(a), "l"(b));
}
__device__ __forceinline__ float hsum2(u64 v) {
    float lo, hi; asm("mov.b64 {%0, %1}, %2;" : "=f"(lo), "=f"(hi) : "l"(v));
    return lo + hi;
}
__device__ __forceinline__ void named_bar(int id) {
    asm volatile("bar.sync %0, 64;" :: "r"(id) : "memory");
}

// ---------------------------------------------------------------------------
// Prep (unchanged; ~15-18us).
// ---------------------------------------------------------------------------
__global__ __launch_bounds__(256, 1) void prep_kernel(
    const float* __restrict__ X,
    const float* __restrict__ h1w,
    const float* __restrict__ h1b,
    const float* __restrict__ g1w)
{
    __shared__ __align__(16) float s_hx[4][64];

    int tid = threadIdx.x;
    int g = tid >> 6;
    int j = tid & 63;

    float wh[16];
#pragma unroll
    for (int k = 0; k < 16; k++) wh[k] = h1w[k * 64 + j];

    u64 wt2[32], wb2[32];
#pragma unroll
    for (int k2 = 0; k2 < 32; k2++) {
        wt2[k2] = pack2(g1w[(2 * k2) * 64 + j],      g1w[(2 * k2 + 1) * 64 + j]);
        wb2[k2] = pack2(g1w[(64 + 2 * k2) * 64 + j], g1w[(64 + 2 * k2 + 1) * 64 + j]);
    }
    float bj = h1b[j];

    const int NGROUPS = L_NODES / 4;   // 7500
    for (int grp = blockIdx.x; grp < NGROUPS; grp += gridDim.x) {
        int l = grp * 4 + g;

        const float4* xr = (const float4*)(X + l * NFEAT);
        float4 x0 = xr[0], x1 = xr[1], x2 = xr[2], x3 = xr[3];
        float acc = bj;
        acc = fmaf(x0.x, wh[ 0], acc); acc = fmaf(x0.y, wh[ 1], acc);
        acc = fmaf(x0.z, wh[ 2], acc); acc = fmaf(x0.w, wh[ 3], acc);
        acc = fmaf(x1.x, wh[ 4], acc); acc = fmaf(x1.y, wh[ 5], acc);
        acc = fmaf(x1.z, wh[ 6], acc); acc = fmaf(x1.w, wh[ 7], acc);
        acc = fmaf(x2.x, wh[ 8], acc); acc = fmaf(x2.y, wh[ 9], acc);
        acc = fmaf(x2.z, wh[10], acc); acc = fmaf(x2.w, wh[11], acc);
        acc = fmaf(x3.x, wh[12], acc); acc = fmaf(x3.y, wh[13], acc);
        acc = fmaf(x3.z, wh[14], acc); acc = fmaf(x3.w, wh[15], acc);
        s_hx[g][j] = fmaxf(acc, 0.0f);
        __syncthreads();

        u64 at2 = 0ull, ab2 = 0ull;
        const ulonglong2* vp = (const ulonglong2*)s_hx[g];
#pragma unroll
        for (int k4 = 0; k4 < 16; k4++) {
            ulonglong2 v = vp[k4];
            int r = 2 * k4;
            ffma2(at2, wt2[r], v.x);      ffma2(ab2, wb2[r], v.x);
            ffma2(at2, wt2[r + 1], v.y);  ffma2(ab2, wb2[r + 1], v.y);
        }
        g_hXWt[l * 64 + j] = hsum2(at2);
        g_hXWb[l * 64 + j] = hsum2(ab2);
        __syncthreads();
    }
}

// ---------------------------------------------------------------------------
// Main (R16): WARP-SPECIALIZED PIPELINE.
// Warps 0-3 = stage A (pairs -> PWb matvecs -> triple vectors), warps 4-7 =
// stage B (TWb matvecs -> quad -> E -> E2 -> head). A-warp w pairs with
// B-warp w+4 on the SAME SMSP; they exchange triple vectors through a
// double-buffered smem slot with ONE named barrier per group. Because A and
// B execute different code, their fma bursts / LDS streams / latency waits
// interleave on the shared SMSP instead of phase-locking.
// Group = 2 nodes. Each warp-pair strides over groups (4*gridDim apart).
// ---------------------------------------------------------------------------
__global__ __launch_bounds__(256, 1) void ggcn_main_kernel(
    const int*   __restrict__ nbr,
    const float* __restrict__ g1w,
    const float* __restrict__ g1b,
    const float* __restrict__ fw,
    const float* __restrict__ fb,
    float*       __restrict__ out)
{
    // A-warp private pair staging, A->B triple handoff (double-buffered),
    // B-warp private E staging.
    __shared__ __align__(16) float s_pair[4][2][6][64];      // 12KB
    __shared__ __align__(16) float s_tri[4][2][2][4][64];    // 16KB [aw][slot][node][m][j]
    __shared__ __align__(16) float s_e[4][2][64];            //  2KB

    int warp = threadIdx.x >> 5;
    int t    = threadIdx.x & 31;
    int aw   = warp & 3;               // pair index within block (SMSP id)
    int p    = blockIdx.x * 4 + aw;    // global warp-pair index
    int STRIDE = gridDim.x * 4;        // 592

    // ---- prologue (both stages need full Wb) ----
    u64 wlo[32], whi[32];
#pragma unroll
    for (int k2 = 0; k2 < 32; k2++) {
        wlo[k2] = pack2(g1w[(64 + 2 * k2) * 64 + t],
                        g1w[(64 + 2 * k2 + 1) * 64 + t]);
        whi[k2] = pack2(g1w[(64 + 2 * k2) * 64 + t + 32],
                        g1w[(64 + 2 * k2 + 1) * 64 + t + 32]);
    }
    float blo = g1b[t], bhi = g1b[t + 32];

    const int PA[6] = {0, 0, 0, 1, 1, 2};
    const int PB[6] = {1, 2, 3, 2, 3, 3};
    const int CP1[3] = {0, 1, 2};
    const int CP2[3] = {5, 4, 3};
    const int C1A[3] = {2, 1, 1};
    const int C1B[3] = {3, 3, 2};
    const int C2A[3] = {0, 0, 0};
    const int C2B[3] = {1, 2, 3};

    if (warp < 4) {
        // =================== STAGE A: pairs -> PWb -> triples ===============
        int slot = 0;
        int4 nbA = ((const int4*)nbr)[p * 2];
        int4 nbB = ((const int4*)nbr)[p * 2 + 1];

        for (int grp = p; grp < NPAIRS; grp += STRIDE) {
            int niA[4] = {nbA.x, nbA.y, nbA.z, nbA.w};
            int niB[4] = {nbB.x, nbB.y, nbB.z, nbB.w};

            float Aib0l[4], Aib0h[4], Aib1l[4], Aib1h[4];
#pragma unroll
            for (int i = 0; i < 4; i++) {
                Aib0l[i] = g_hXWt[niA[i] * 64 + t]      + blo;
                Aib0h[i] = g_hXWt[niA[i] * 64 + t + 32] + bhi;
                Aib1l[i] = g_hXWt[niB[i] * 64 + t]      + blo;
                Aib1h[i] = g_hXWt[niB[i] * 64 + t + 32] + bhi;
            }

            // ---- pairs ----
            {
                float B0l[4], B0h[4], B1l[4], B1h[4];
#pragma unroll
                for (int i = 0; i < 4; i++) {
                    B0l[i] = g_hXWb[niA[i] * 64 + t];
                    B0h[i] = g_hXWb[niA[i] * 64 + t + 32];
                    B1l[i] = g_hXWb[niB[i] * 64 + t];
                    B1h[i] = g_hXWb[niB[i] * 64 + t + 32];
                }
#pragma unroll
                for (int pp = 0; pp < 6; pp++) {
                    int i0 = PA[pp], i1 = PB[pp];
                    s_pair[aw][0][pp][t] =
                        0.5f * (fmaxf(Aib0l[i0] + B0l[i1], 0.0f) +
                                fmaxf(Aib0l[i1] + B0l[i0], 0.0f));
                    s_pair[aw][0][pp][t + 32] =
                        0.5f * (fmaxf(Aib0h[i0] + B0h[i1], 0.0f) +
                                fmaxf(Aib0h[i1] + B0h[i0], 0.0f));
                    s_pair[aw][1][pp][t] =
                        0.5f * (fmaxf(Aib1l[i0] + B1l[i1], 0.0f) +
                                fmaxf(Aib1l[i1] + B1l[i0], 0.0f));
                    s_pair[aw][1][pp][t + 32] =
                        0.5f * (fmaxf(Aib1h[i0] + B1h[i1], 0.0f) +
                                fmaxf(Aib1h[i1] + B1h[i0], 0.0f));
                }
            }

            // prefetch next group's neighbors
            {
                int ng = grp + STRIDE;
                int safe = (ng < NPAIRS) ? ng : grp;
                nbA = ((const int4*)nbr)[safe * 2];
                nbB = ((const int4*)nbr)[safe * 2 + 1];
            }
            __syncwarp();

            // ---- fused PWb matvecs + triple accumulation ----
            float tr0l[4] = {0.f,0.f,0.f,0.f}, tr0h[4] = {0.f,0.f,0.f,0.f};
            float tr1l[4] = {0.f,0.f,0.f,0.f}, tr1h[4] = {0.f,0.f,0.f,0.f};
#pragma unroll
            for (int cp = 0; cp < 3; cp++) {
                int pp = CP1[cp], qq = CP2[cp];
                u64 a0l = 0ull, a0h = 0ull, a1l = 0ull, a1h = 0ull;
                u64 c0l = 0ull, c0h = 0ull, c1l = 0ull, c1h = 0ull;
                const ulonglong2* vP0 = (const ulonglong2*)s_pair[aw][0][pp];
                const ulonglong2* vQ0 = (const ulonglong2*)s_pair[aw][0][qq];
                const ulonglong2* vP1 = (const ulonglong2*)s_pair[aw][1][pp];
                const ulonglong2* vQ1 = (const ulonglong2*)s_pair[aw][1][qq];
#pragma unroll
                for (int k4 = 0; k4 < 16; k4++) {
                    ulonglong2 P0 = vP0[k4], Q0 = vQ0[k4];
                    ulonglong2 P1 = vP1[k4], Q1 = vQ1[k4];
                    int r = 2 * k4;
                    ffma2(a0l, wlo[r], P0.x);      ffma2(a0h, whi[r], P0.x);
                    ffma2(a0l, wlo[r + 1], P0.y);  ffma2(a0h, whi[r + 1], P0.y);
                    ffma2(c0l, wlo[r], Q0.x);      ffma2(c0h, whi[r], Q0.x);
                    ffma2(c0l, wlo[r + 1], Q0.y);  ffma2(c0h, whi[r + 1], Q0.y);
                    ffma2(a1l, wlo[r], P1.x);      ffma2(a1h, whi[r], P1.x);
                    ffma2(a1l, wlo[r + 1], P1.y);  ffma2(a1h, whi[r + 1], P1.y);
                    ffma2(c1l, wlo[r], Q1.x);      ffma2(c1h, whi[r], Q1.x);
                    ffma2(c1l, wlo[r + 1], Q1.y);  ffma2(c1h, whi[r + 1], Q1.y);
                }
                float pw0l = hsum2(a0l), pw0h = hsum2(a0h);
                float qw0l = hsum2(c0l), qw0h = hsum2(c0h);
                float pw1l = hsum2(a1l), pw1h = hsum2(a1h);
                float qw1l = hsum2(c1l), qw1h = hsum2(c1h);

                int u = C1A[cp], v = C1B[cp];
                int x = C2A[cp], y = C2B[cp];
                tr0l[u] += fmaxf(Aib0l[v] + pw0l, 0.0f);
                tr0l[v] += fmaxf(Aib0l[u] + pw0l, 0.0f);
                tr0h[u] += fmaxf(Aib0h[v] + pw0h, 0.0f);
                tr0h[v] += fmaxf(Aib0h[u] + pw0h, 0.0f);
                tr0l[x] += fmaxf(Aib0l[y] + qw0l, 0.0f);
                tr0l[y] += fmaxf(Aib0l[x] + qw0l, 0.0f);
                tr0h[x] += fmaxf(Aib0h[y] + qw0h, 0.0f);
                tr0h[y] += fmaxf(Aib0h[x] + qw0h, 0.0f);
                tr1l[u] += fmaxf(Aib1l[v] + pw1l, 0.0f);
                tr1l[v] += fmaxf(Aib1l[u] + pw1l, 0.0f);
                tr1h[u] += fmaxf(Aib1h[v] + pw1h, 0.0f);
                tr1h[v] += fmaxf(Aib1h[u] + pw1h, 0.0f);
                tr1l[x] += fmaxf(Aib1l[y] + qw1l, 0.0f);
                tr1l[y] += fmaxf(Aib1l[x] + qw1l, 0.0f);
                tr1h[x] += fmaxf(Aib1h[y] + qw1h, 0.0f);
                tr1h[y] += fmaxf(Aib1h[x] + qw1h, 0.0f);
            }

            // ---- publish triple vectors to the handoff slot ----
#pragma unroll
            for (int m = 0; m < 4; m++) {
                s_tri[aw][slot][0][m][t]      = tr0l[m] * (1.0f / 3.0f);
                s_tri[aw][slot][0][m][t + 32] = tr0h[m] * (1.0f / 3.0f);
                s_tri[aw][slot][1][m][t]      = tr1l[m] * (1.0f / 3.0f);
                s_tri[aw][slot][1][m][t + 32] = tr1h[m] * (1.0f / 3.0f);
            }
            named_bar(1 + aw);
            slot ^= 1;
            __syncwarp();   // s_pair reuse next iteration
        }
    } else {
        // =================== STAGE B: TWb -> quad -> E -> E2 -> head ========
        float fwl0 = fw[t * 2 + 0],        fwl1 = fw[t * 2 + 1];
        float fwh0 = fw[(t + 32) * 2 + 0], fwh1 = fw[(t + 32) * 2 + 1];
        float fb0 = fb[0], fb1 = fb[1];

        int slot = 0;
        int4 nbA = ((const int4*)nbr)[p * 2];
        int4 nbB = ((const int4*)nbr)[p * 2 + 1];

        for (int grp = p; grp < NPAIRS; grp += STRIDE) {
            int l0 = grp * 2, l1 = l0 + 1;
            int niA[4] = {nbA.x, nbA.y, nbA.z, nbA.w};
            int niB[4] = {nbB.x, nbB.y, nbB.z, nbB.w};

            // recompute Aib (cheaper than register handoff; L2-resident)
            float Aib0l[4], Aib0h[4], Aib1l[4], Aib1h[4];
#pragma unroll
            for (int i = 0; i < 4; i++) {
                Aib0l[i] = g_hXWt[niA[i] * 64 + t]      + blo;
                Aib0h[i] = g_hXWt[niA[i] * 64 + t + 32] + bhi;
                Aib1l[i] = g_hXWt[niB[i] * 64 + t]      + blo;
                Aib1h[i] = g_hXWt[niB[i] * 64 + t + 32] + bhi;
            }
            float hx0l = g_hXWt[l0 * 64 + t], hx0h = g_hXWt[l0 * 64 + t + 32];
            float hx1l = g_hXWt[l1 * 64 + t], hx1h = g_hXWt[l1 * 64 + t + 32];

            // prefetch next group's neighbors
            {
                int ng = grp + STRIDE;
                int safe = (ng < NPAIRS) ? ng : grp;
                nbA = ((const int4*)nbr)[safe * 2];
                nbB = ((const int4*)nbr)[safe * 2 + 1];
            }

            named_bar(1 + aw);   // wait for A's slot fill

            // ---- fused TWb matvecs + quad ----
            float q0l = 0.f, q0h = 0.f, q1l = 0.f, q1h = 0.f;
#pragma unroll
            for (int m = 0; m < 4; m += 2) {
                u64 a0l = 0ull, a0h = 0ull, a1l = 0ull, a1h = 0ull;
                u64 c0l = 0ull, c0h = 0ull, c1l = 0ull, c1h = 0ull;
                const ulonglong2* v0A = (const ulonglong2*)s_tri[aw][slot][0][m];
                const ulonglong2* v1A = (const ulonglong2*)s_tri[aw][slot][0][m + 1];
                const ulonglong2* v0B = (const ulonglong2*)s_tri[aw][slot][1][m];
                const ulonglong2* v1B = (const ulonglong2*)s_tri[aw][slot][1][m + 1];
#pragma unroll
                for (int k4 = 0; k4 < 16; k4++) {
                    ulonglong2 VA = v0A[k4], UA = v1A[k4];
                    ulonglong2 VB = v0B[k4], UB = v1B[k4];
                    int r = 2 * k4;
                    ffma2(a0l, wlo[r], VA.x);      ffma2(a0h, whi[r], VA.x);
                    ffma2(a0l, wlo[r + 1], VA.y);  ffma2(a0h, whi[r + 1], VA.y);
                    ffma2(a1l, wlo[r], UA.x);      ffma2(a1h, whi[r], UA.x);
                    ffma2(a1l, wlo[r + 1], UA.y);  ffma2(a1h, whi[r + 1], UA.y);
                    ffma2(c0l, wlo[r], VB.x);      ffma2(c0h, whi[r], VB.x);
                    ffma2(c0l, wlo[r + 1], VB.y);  ffma2(c0h, whi[r + 1], VB.y);
                    ffma2(c1l, wlo[r], UB.x);      ffma2(c1h, whi[r], UB.x);
                    ffma2(c1l, wlo[r + 1], UB.y);  ffma2(c1h, whi[r + 1], UB.y);
                }
                q0l += fmaxf(Aib0l[m] + hsum2(a0l), 0.0f)
                     + fmaxf(Aib0l[m + 1] + hsum2(a1l), 0.0f);
                q0h += fmaxf(Aib0h[m] + hsum2(a0h), 0.0f)
                     + fmaxf(Aib0h[m + 1] + hsum2(a1h), 0.0f);
                q1l += fmaxf(Aib1l[m] + hsum2(c0l), 0.0f)
                     + fmaxf(Aib1l[m + 1] + hsum2(c1l), 0.0f);
                q1h += fmaxf(Aib1h[m] + hsum2(c0h), 0.0f)
                     + fmaxf(Aib1h[m + 1] + hsum2(c1h), 0.0f);
            }
            slot ^= 1;

            // ---- E vector (B-private staging) ----
            int bw = aw;
            s_e[bw][0][t]      = fmaxf(q0l * 0.25f, 0.0f);
            s_e[bw][0][t + 32] = fmaxf(q0h * 0.25f, 0.0f);
            s_e[bw][1][t]      = fmaxf(q1l * 0.25f, 0.0f);
            s_e[bw][1][t + 32] = fmaxf(q1h * 0.25f, 0.0f);
            __syncwarp();

            // ---- E2 = relu(hxwt + E@Wb + b) ----
            u64 e0l = 0ull, e0h = 0ull, e1l = 0ull, e1h = 0ull;
            {
                const ulonglong2* vA = (const ulonglong2*)s_e[bw][0];
                const ulonglong2* vB = (const ulonglong2*)s_e[bw][1];
#pragma unroll
                for (int k4 = 0; k4 < 16; k4++) {
                    ulonglong2 a = vA[k4], b = vB[k4];
                    int r = 2 * k4;
                    ffma2(e0l, wlo[r], a.x);      ffma2(e0h, whi[r], a.x);
                    ffma2(e0l, wlo[r + 1], a.y);  ffma2(e0h, whi[r + 1], a.y);
                    ffma2(e1l, wlo[r], b.x);      ffma2(e1h, whi[r], b.x);
                    ffma2(e1l, wlo[r + 1], b.y);  ffma2(e1h, whi[r + 1], b.y);
                }
            }
            float E20l = fmaxf(hx0l + hsum2(e0l) + blo, 0.0f);
            float E20h = fmaxf(hx0h + hsum2(e0h) + bhi, 0.0f);
            float E21l = fmaxf(hx1l + hsum2(e1l) + blo, 0.0f);
            float E21h = fmaxf(hx1h + hsum2(e1h) + bhi, 0.0f);

            // ---- readout head ----
            float p0 = E20l * fwl0 + E20h * fwh0;
            float p1 = E20l * fwl1 + E20h * fwh1;
            float r0 = E21l * fwl0 + E21h * fwh0;
            float r1 = E21l * fwl1 + E21h * fwh1;
#pragma unroll
            for (int off = 16; off > 0; off >>= 1) {
                p0 += __shfl_xor_sync(0xffffffffu, p0, off);
                p1 += __shfl_xor_sync(0xffffffffu, p1, off);
                r0 += __shfl_xor_sync(0xffffffffu, r0, off);
                r1 += __shfl_xor_sync(0xffffffffu, r1, off);
            }
            if (t == 0) {
                float2 oA = {p0 + fb0, p1 + fb1};
                float2 oB = {r0 + fb0, r1 + fb1};
                *(float2*)(out + l0 * 2) = oA;
                *(float2*)(out + l1 * 2) = oB;
            }
            __syncwarp();   // s_e reuse next iteration
        }
    }
}

// ---------------------------------------------------------------------------
// kernel_launch: graph-capturable, allocation-free.
// Inputs: X, neighbors, h1_w, h1_b, g1_w, g1_b, final_w, final_b
// ---------------------------------------------------------------------------
extern "C" void kernel_launch(void* const* d_in, const int* in_sizes, int n_in,
                              void* d_out, int out_size)
{
    const float* X    = (const float*)d_in[0];
    const int*   nbr  = (const int*)  d_in[1];
    const float* h1w  = (const float*)d_in[2];
    const float* h1b  = (const float*)d_in[3];
    const float* g1w  = (const float*)d_in[4];
    const float* g1b  = (const float*)d_in[5];
    const float* fw   = (const float*)d_in[6];
    const float* fb   = (const float*)d_in[7];
    float* out = (float*)d_out;

    (void)in_sizes; (void)n_in; (void)out_size;

    prep_kernel<<<296, 256>>>(X, h1w, h1b, g1w);
    ggcn_main_kernel<<<148, 256>>>(nbr, g1w, g1b, fw, fb, out);
}

// round 17
// speedup vs baseline: 1.1024x; 1.1024x over previous
#include <cuda_runtime.h>

#define L_NODES 30000
#define JDIM 64
#define NFEAT 16

// Scratch (allocation-free): per-node tables.
__device__ float g_hXWt[L_NODES * JDIM];
__device__ float g_hXWb[L_NODES * JDIM];

typedef unsigned long long u64;

// ---- packed f32x2 helpers (sm_100+) ----------------------------------------
__device__ __forceinline__ u64 pack2(float lo, float hi) {
    u64 r; asm("mov.b64 %0, {%1, %2};" : "=l"(r) : "f"(lo), "f"(hi)); return r;
}
__device__ __forceinline__ void ffma2(u64& d, u64 a, u64 b) {
    asm("fma.rn.f32x2 %0, %1, %2, %0;" : "+l"(d) : "l"(a), "l"(b));
}
__device__ __forceinline__ float hsum2(u64 v) {
    float lo, hi; asm("mov.b64 {%0, %1}, %2;" : "=f"(lo), "=f"(hi) : "l"(v));
    return lo + hi;
}
__device__ __forceinline__ void named_bar64(int id) {
    asm volatile("bar.sync %0, 64;" :: "r"(id) : "memory");
}

// ---------------------------------------------------------------------------
// Prep (R17): k-split across a warp PAIR. Node n <-> warps {n, n+4}; warp h
// owns k in [32h,32h+32) with ALL FOUR weight columns for that half
// (4 cols x 16 k2 = 64 u64 regs), computes hx for j in [32h,32h+32) so each
// warp reads only the hx half it wrote (__syncwarp, no cross-warp hx sync).
// Streamed words/node: 64 (was 128). Partials combined via parity-double-
// buffered smem + one named barrier per iteration.
// ---------------------------------------------------------------------------
__global__ __launch_bounds__(256, 1) void prep_kernel(
    const float* __restrict__ X,
    const float* __restrict__ h1w,
    const float* __restrict__ h1b,
    const float* __restrict__ g1w)
{
    __shared__ __align__(16) float s_hx[4][64];
    __shared__ float s_part[4][2][4][32];   // [node][parity][quantity][lane]

    int warp = threadIdx.x >> 5;
    int t    = threadIdx.x & 31;
    int n    = warp & 3;    // node slot
    int h    = warp >> 2;   // k-half
    int j    = 32 * h + t;  // hx column this thread computes

    // hx weights: column j
    float wh[16];
#pragma unroll
    for (int k = 0; k < 16; k++) wh[k] = h1w[k * 64 + j];
    float bj = h1b[j];

    // matvec weights: cols {t, t+32} of Wt and Wb, k in [32h, 32h+32)
    u64 wt2[2][16], wb2[2][16];
#pragma unroll
    for (int k2 = 0; k2 < 16; k2++) {
        int kk = 32 * h + 2 * k2;
        wt2[0][k2] = pack2(g1w[kk * 64 + t],        g1w[(kk + 1) * 64 + t]);
        wt2[1][k2] = pack2(g1w[kk * 64 + t + 32],   g1w[(kk + 1) * 64 + t + 32]);
        wb2[0][k2] = pack2(g1w[(64 + kk) * 64 + t],      g1w[(64 + kk + 1) * 64 + t]);
        wb2[1][k2] = pack2(g1w[(64 + kk) * 64 + t + 32], g1w[(64 + kk + 1) * 64 + t + 32]);
    }

    const int NGROUPS = L_NODES / 4;   // 7500
    int par = 0;
    for (int grp = blockIdx.x; grp < NGROUPS; grp += gridDim.x) {
        int l = grp * 4 + n;

        // hx_j = relu(X[l] @ h1w[:,j] + b_j); X row broadcast.
        const float4* xr = (const float4*)(X + l * NFEAT);
        float4 x0 = xr[0], x1 = xr[1], x2 = xr[2], x3 = xr[3];
        float acc = bj;
        acc = fmaf(x0.x, wh[ 0], acc); acc = fmaf(x0.y, wh[ 1], acc);
        acc = fmaf(x0.z, wh[ 2], acc); acc = fmaf(x0.w, wh[ 3], acc);
        acc = fmaf(x1.x, wh[ 4], acc); acc = fmaf(x1.y, wh[ 5], acc);
        acc = fmaf(x1.z, wh[ 6], acc); acc = fmaf(x1.w, wh[ 7], acc);
        acc = fmaf(x2.x, wh[ 8], acc); acc = fmaf(x2.y, wh[ 9], acc);
        acc = fmaf(x2.z, wh[10], acc); acc = fmaf(x2.w, wh[11], acc);
        acc = fmaf(x3.x, wh[12], acc); acc = fmaf(x3.y, wh[13], acc);
        acc = fmaf(x3.z, wh[14], acc); acc = fmaf(x3.w, wh[15], acc);
        s_hx[n][j] = fmaxf(acc, 0.0f);
        __syncwarp();   // warp reads only its own half below

        // half-dot over k in [32h, 32h+32) for 4 output columns
        u64 awt0 = 0ull, awt1 = 0ull, awb0 = 0ull, awb1 = 0ull;
        const ulonglong2* vp = (const ulonglong2*)(s_hx[n] + 32 * h);
#pragma unroll
        for (int k4 = 0; k4 < 8; k4++) {
            ulonglong2 v = vp[k4];
            int r = 2 * k4;
            ffma2(awt0, wt2[0][r], v.x);      ffma2(awt1, wt2[1][r], v.x);
            ffma2(awb0, wb2[0][r], v.x);      ffma2(awb1, wb2[1][r], v.x);
            ffma2(awt0, wt2[0][r + 1], v.y);  ffma2(awt1, wt2[1][r + 1], v.y);
            ffma2(awb0, wb2[0][r + 1], v.y);  ffma2(awb1, wb2[1][r + 1], v.y);
        }
        float pwt0 = hsum2(awt0), pwt1 = hsum2(awt1);
        float pwb0 = hsum2(awb0), pwb1 = hsum2(awb1);

        if (h == 1) {
            s_part[n][par][0][t] = pwt0;
            s_part[n][par][1][t] = pwt1;
            s_part[n][par][2][t] = pwb0;
            s_part[n][par][3][t] = pwb1;
        }
        named_bar64(1 + n);
        if (h == 0) {
            g_hXWt[l * 64 + t]      = pwt0 + s_part[n][par][0][t];
            g_hXWt[l * 64 + t + 32] = pwt1 + s_part[n][par][1][t];
            g_hXWb[l * 64 + t]      = pwb0 + s_part[n][par][2][t];
            g_hXWb[l * 64 + t + 32] = pwb1 + s_part[n][par][3][t];
        }
        par ^= 1;   // double-buffer s_part; no second barrier needed
    }
}

// ---------------------------------------------------------------------------
// Main (R17): R15 structure (proven 81.0us) + cross-group A/hx prefetch.
// After the pairs stage (B regs dead), next group's 16 A-table gathers and
// 4 hx loads issue into registers using the already-prefetched nbr; they
// complete under ~6K cycles of matvec compute, so the next iteration head
// is pure FADDs instead of an exposed L2 chain.
// ---------------------------------------------------------------------------
__global__ __launch_bounds__(256, 1) void ggcn_main_kernel(
    const int*   __restrict__ nbr,
    const float* __restrict__ g1w,
    const float* __restrict__ g1b,
    const float* __restrict__ fw,
    const float* __restrict__ fb,
    float*       __restrict__ out)
{
    __shared__ __align__(16) float s_v[8][2][6][64];   // [warp][node][vec][j]

    int warp = threadIdx.x >> 5;
    int t    = threadIdx.x & 31;

    // ---- prologue (once per block) ----
    u64 wlo[32], whi[32];
#pragma unroll
    for (int k2 = 0; k2 < 32; k2++) {
        wlo[k2] = pack2(g1w[(64 + 2 * k2) * 64 + t],
                        g1w[(64 + 2 * k2 + 1) * 64 + t]);
        whi[k2] = pack2(g1w[(64 + 2 * k2) * 64 + t + 32],
                        g1w[(64 + 2 * k2 + 1) * 64 + t + 32]);
    }
    float blo = g1b[t], bhi = g1b[t + 32];
    float fwl0 = fw[t * 2 + 0],        fwl1 = fw[t * 2 + 1];
    float fwh0 = fw[(t + 32) * 2 + 0], fwh1 = fw[(t + 32) * 2 + 1];
    float fb0 = fb[0], fb1 = fb[1];

    const int PA[6] = {0, 0, 0, 1, 1, 2};
    const int PB[6] = {1, 2, 3, 2, 3, 3};
    const int CP1[3] = {0, 1, 2};
    const int CP2[3] = {5, 4, 3};
    const int C1A[3] = {2, 1, 1};
    const int C1B[3] = {3, 3, 2};
    const int C2A[3] = {0, 0, 0};
    const int C2B[3] = {1, 2, 3};

    const int NGRP = L_NODES / 16;   // 1875

    // ---- first-iteration prefetch: nbr, A gathers, hx ----
    int4 nbA, nbB;
    float pA0l[4], pA0h[4], pA1l[4], pA1h[4];
    float phx0l, phx0h, phx1l, phx1h;
    {
        int l0f = blockIdx.x * 16 + warp * 2;
        nbA = ((const int4*)nbr)[l0f];
        nbB = ((const int4*)nbr)[l0f + 1];
        int fA[4] = {nbA.x, nbA.y, nbA.z, nbA.w};
        int fB[4] = {nbB.x, nbB.y, nbB.z, nbB.w};
#pragma unroll
        for (int i = 0; i < 4; i++) {
            pA0l[i] = g_hXWt[fA[i] * 64 + t];
            pA0h[i] = g_hXWt[fA[i] * 64 + t + 32];
            pA1l[i] = g_hXWt[fB[i] * 64 + t];
            pA1h[i] = g_hXWt[fB[i] * 64 + t + 32];
        }
        phx0l = g_hXWt[l0f * 64 + t];
        phx0h = g_hXWt[l0f * 64 + t + 32];
        phx1l = g_hXWt[(l0f + 1) * 64 + t];
        phx1h = g_hXWt[(l0f + 1) * 64 + t + 32];
    }

    for (int grp = blockIdx.x; grp < NGRP; grp += gridDim.x) {
        int l0 = grp * 16 + warp * 2;
        int l1 = l0 + 1;

        int niA[4] = {nbA.x, nbA.y, nbA.z, nbA.w};
        int niB[4] = {nbB.x, nbB.y, nbB.z, nbB.w};

        // Aib from prefetched A values (no LDG at head)
        float Aib0l[4], Aib0h[4], Aib1l[4], Aib1h[4];
#pragma unroll
        for (int i = 0; i < 4; i++) {
            Aib0l[i] = pA0l[i] + blo;
            Aib0h[i] = pA0h[i] + bhi;
            Aib1l[i] = pA1l[i] + blo;
            Aib1h[i] = pA1h[i] + bhi;
        }
        float hx0l = phx0l, hx0h = phx0h, hx1l = phx1l, hx1h = phx1h;

        // ---- pairs (B gathers synchronous; B regs die here) ----
        {
            float B0l[4], B0h[4], B1l[4], B1h[4];
#pragma unroll
            for (int i = 0; i < 4; i++) {
                B0l[i] = g_hXWb[niA[i] * 64 + t];
                B0h[i] = g_hXWb[niA[i] * 64 + t + 32];
                B1l[i] = g_hXWb[niB[i] * 64 + t];
                B1h[i] = g_hXWb[niB[i] * 64 + t + 32];
            }
#pragma unroll
            for (int p = 0; p < 6; p++) {
                int i0 = PA[p], i1 = PB[p];
                s_v[warp][0][p][t] =
                    0.5f * (fmaxf(Aib0l[i0] + B0l[i1], 0.0f) +
                            fmaxf(Aib0l[i1] + B0l[i0], 0.0f));
                s_v[warp][0][p][t + 32] =
                    0.5f * (fmaxf(Aib0h[i0] + B0h[i1], 0.0f) +
                            fmaxf(Aib0h[i1] + B0h[i0], 0.0f));
                s_v[warp][1][p][t] =
                    0.5f * (fmaxf(Aib1l[i0] + B1l[i1], 0.0f) +
                            fmaxf(Aib1l[i1] + B1l[i0], 0.0f));
                s_v[warp][1][p][t + 32] =
                    0.5f * (fmaxf(Aib1h[i0] + B1h[i1], 0.0f) +
                            fmaxf(Aib1h[i1] + B1h[i0], 0.0f));
            }
        }

        // ---- prefetch next group's nbr, then A gathers + hx ----
        {
            int ng = grp + gridDim.x;
            int safe = (ng < NGRP) ? ng : grp;
            int lp = safe * 16 + warp * 2;
            nbA = ((const int4*)nbr)[lp];
            nbB = ((const int4*)nbr)[lp + 1];
            int nA[4] = {nbA.x, nbA.y, nbA.z, nbA.w};
            int nB[4] = {nbB.x, nbB.y, nbB.z, nbB.w};
#pragma unroll
            for (int i = 0; i < 4; i++) {
                pA0l[i] = g_hXWt[nA[i] * 64 + t];
                pA0h[i] = g_hXWt[nA[i] * 64 + t + 32];
                pA1l[i] = g_hXWt[nB[i] * 64 + t];
                pA1h[i] = g_hXWt[nB[i] * 64 + t + 32];
            }
            phx0l = g_hXWt[lp * 64 + t];
            phx0h = g_hXWt[lp * 64 + t + 32];
            phx1l = g_hXWt[(lp + 1) * 64 + t];
            phx1h = g_hXWt[(lp + 1) * 64 + t + 32];
        }
        __syncwarp();

        // ---- fused PWb matvecs + triple accumulation ----
        float tr0l[4] = {0.f,0.f,0.f,0.f}, tr0h[4] = {0.f,0.f,0.f,0.f};
        float tr1l[4] = {0.f,0.f,0.f,0.f}, tr1h[4] = {0.f,0.f,0.f,0.f};
#pragma unroll
        for (int cp = 0; cp < 3; cp++) {
            int p = CP1[cp], q = CP2[cp];
            u64 a0l = 0ull, a0h = 0ull, a1l = 0ull, a1h = 0ull;
            u64 c0l = 0ull, c0h = 0ull, c1l = 0ull, c1h = 0ull;
            const ulonglong2* vP0 = (const ulonglong2*)s_v[warp][0][p];
            const ulonglong2* vQ0 = (const ulonglong2*)s_v[warp][0][q];
            const ulonglong2* vP1 = (const ulonglong2*)s_v[warp][1][p];
            const ulonglong2* vQ1 = (const ulonglong2*)s_v[warp][1][q];
#pragma unroll
            for (int k4 = 0; k4 < 16; k4++) {
                ulonglong2 P0 = vP0[k4], Q0 = vQ0[k4];
                ulonglong2 P1 = vP1[k4], Q1 = vQ1[k4];
                int r = 2 * k4;
                ffma2(a0l, wlo[r], P0.x);      ffma2(a0h, whi[r], P0.x);
                ffma2(a0l, wlo[r + 1], P0.y);  ffma2(a0h, whi[r + 1], P0.y);
                ffma2(c0l, wlo[r], Q0.x);      ffma2(c0h, whi[r], Q0.x);
                ffma2(c0l, wlo[r + 1], Q0.y);  ffma2(c0h, whi[r + 1], Q0.y);
                ffma2(a1l, wlo[r], P1.x);      ffma2(a1h, whi[r], P1.x);
                ffma2(a1l, wlo[r + 1], P1.y);  ffma2(a1h, whi[r + 1], P1.y);
                ffma2(c1l, wlo[r], Q1.x);      ffma2(c1h, whi[r], Q1.x);
                ffma2(c1l, wlo[r + 1], Q1.y);  ffma2(c1h, whi[r + 1], Q1.y);
            }
            float pw0l = hsum2(a0l), pw0h = hsum2(a0h);
            float qw0l = hsum2(c0l), qw0h = hsum2(c0h);
            float pw1l = hsum2(a1l), pw1h = hsum2(a1h);
            float qw1l = hsum2(c1l), qw1h = hsum2(c1h);

            int u = C1A[cp], v = C1B[cp];
            int x = C2A[cp], y = C2B[cp];
            tr0l[u] += fmaxf(Aib0l[v] + pw0l, 0.0f);
            tr0l[v] += fmaxf(Aib0l[u] + pw0l, 0.0f);
            tr0h[u] += fmaxf(Aib0h[v] + pw0h, 0.0f);
            tr0h[v] += fmaxf(Aib0h[u] + pw0h, 0.0f);
            tr0l[x] += fmaxf(Aib0l[y] + qw0l, 0.0f);
            tr0l[y] += fmaxf(Aib0l[x] + qw0l, 0.0f);
            tr0h[x] += fmaxf(Aib0h[y] + qw0h, 0.0f);
            tr0h[y] += fmaxf(Aib0h[x] + qw0h, 0.0f);
            tr1l[u] += fmaxf(Aib1l[v] + pw1l, 0.0f);
            tr1l[v] += fmaxf(Aib1l[u] + pw1l, 0.0f);
            tr1h[u] += fmaxf(Aib1h[v] + pw1h, 0.0f);
            tr1h[v] += fmaxf(Aib1h[u] + pw1h, 0.0f);
            tr1l[x] += fmaxf(Aib1l[y] + qw1l, 0.0f);
            tr1l[y] += fmaxf(Aib1l[x] + qw1l, 0.0f);
            tr1h[x] += fmaxf(Aib1h[y] + qw1h, 0.0f);
            tr1h[y] += fmaxf(Aib1h[x] + qw1h, 0.0f);
        }
        __syncwarp();

        // ---- stage triple vectors ----
#pragma unroll
        for (int m = 0; m < 4; m++) {
            s_v[warp][0][m][t]      = tr0l[m] * (1.0f / 3.0f);
            s_v[warp][0][m][t + 32] = tr0h[m] * (1.0f / 3.0f);
            s_v[warp][1][m][t]      = tr1l[m] * (1.0f / 3.0f);
            s_v[warp][1][m][t + 32] = tr1h[m] * (1.0f / 3.0f);
        }
        __syncwarp();

        // ---- fused TWb matvecs + quad accumulation ----
        float q0l = 0.f, q0h = 0.f, q1l = 0.f, q1h = 0.f;
#pragma unroll
        for (int m = 0; m < 4; m += 2) {
            u64 a0l = 0ull, a0h = 0ull, a1l = 0ull, a1h = 0ull;
            u64 c0l = 0ull, c0h = 0ull, c1l = 0ull, c1h = 0ull;
            const ulonglong2* v0A = (const ulonglong2*)s_v[warp][0][m];
            const ulonglong2* v1A = (const ulonglong2*)s_v[warp][0][m + 1];
            const ulonglong2* v0B = (const ulonglong2*)s_v[warp][1][m];
            const ulonglong2* v1B = (const ulonglong2*)s_v[warp][1][m + 1];
#pragma unroll
            for (int k4 = 0; k4 < 16; k4++) {
                ulonglong2 VA = v0A[k4], UA = v1A[k4];
                ulonglong2 VB = v0B[k4], UB = v1B[k4];
                int r = 2 * k4;
                ffma2(a0l, wlo[r], VA.x);      ffma2(a0h, whi[r], VA.x);
                ffma2(a0l, wlo[r + 1], VA.y);  ffma2(a0h, whi[r + 1], VA.y);
                ffma2(a1l, wlo[r], UA.x);      ffma2(a1h, whi[r], UA.x);
                ffma2(a1l, wlo[r + 1], UA.y);  ffma2(a1h, whi[r + 1], UA.y);
                ffma2(c0l, wlo[r], VB.x);      ffma2(c0h, whi[r], VB.x);
                ffma2(c0l, wlo[r + 1], VB.y);  ffma2(c0h, whi[r + 1], VB.y);
                ffma2(c1l, wlo[r], UB.x);      ffma2(c1h, whi[r], UB.x);
                ffma2(c1l, wlo[r + 1], UB.y);  ffma2(c1h, whi[r + 1], UB.y);
            }
            q0l += fmaxf(Aib0l[m] + hsum2(a0l), 0.0f)
                 + fmaxf(Aib0l[m + 1] + hsum2(a1l), 0.0f);
            q0h += fmaxf(Aib0h[m] + hsum2(a0h), 0.0f)
                 + fmaxf(Aib0h[m + 1] + hsum2(a1h), 0.0f);
            q1l += fmaxf(Aib1l[m] + hsum2(c0l), 0.0f)
                 + fmaxf(Aib1l[m + 1] + hsum2(c1l), 0.0f);
            q1h += fmaxf(Aib1h[m] + hsum2(c0h), 0.0f)
                 + fmaxf(Aib1h[m + 1] + hsum2(c1h), 0.0f);
        }
        __syncwarp();

        // ---- E vector ----
        s_v[warp][0][0][t]      = fmaxf(q0l * 0.25f, 0.0f);
        s_v[warp][0][0][t + 32] = fmaxf(q0h * 0.25f, 0.0f);
        s_v[warp][1][0][t]      = fmaxf(q1l * 0.25f, 0.0f);
        s_v[warp][1][0][t + 32] = fmaxf(q1h * 0.25f, 0.0f);
        __syncwarp();

        // ---- E2 = relu(hxwt + E@Wb + b) ----
        u64 e0l = 0ull, e0h = 0ull, e1l = 0ull, e1h = 0ull;
        {
            const ulonglong2* vA = (const ulonglong2*)s_v[warp][0][0];
            const ulonglong2* vB = (const ulonglong2*)s_v[warp][1][0];
#pragma unroll
            for (int k4 = 0; k4 < 16; k4++) {
                ulonglong2 a = vA[k4], b = vB[k4];
                int r = 2 * k4;
                ffma2(e0l, wlo[r], a.x);      ffma2(e0h, whi[r], a.x);
                ffma2(e0l, wlo[r + 1], a.y);  ffma2(e0h, whi[r + 1], a.y);
                ffma2(e1l, wlo[r], b.x);      ffma2(e1h, whi[r], b.x);
                ffma2(e1l, wlo[r + 1], b.y);  ffma2(e1h, whi[r + 1], b.y);
            }
        }
        float E20l = fmaxf(hx0l + hsum2(e0l) + blo, 0.0f);
        float E20h = fmaxf(hx0h + hsum2(e0h) + bhi, 0.0f);
        float E21l = fmaxf(hx1l + hsum2(e1l) + blo, 0.0f);
        float E21h = fmaxf(hx1h + hsum2(e1h) + bhi, 0.0f);

        // ---- readout head ----
        float p0 = E20l * fwl0 + E20h * fwh0;
        float p1 = E20l * fwl1 + E20h * fwh1;
        float r0 = E21l * fwl0 + E21h * fwh0;
        float r1 = E21l * fwl1 + E21h * fwh1;
#pragma unroll
        for (int off = 16; off > 0; off >>= 1) {
            p0 += __shfl_xor_sync(0xffffffffu, p0, off);
            p1 += __shfl_xor_sync(0xffffffffu, p1, off);
            r0 += __shfl_xor_sync(0xffffffffu, r0, off);
            r1 += __shfl_xor_sync(0xffffffffu, r1, off);
        }
        if (t == 0) {
            float2 oA = {p0 + fb0, p1 + fb1};
            float2 oB = {r0 + fb0, r1 + fb1};
            *(float2*)(out + l0 * 2) = oA;
            *(float2*)(out + l1 * 2) = oB;
        }
        __syncwarp();   // protect s_v reuse across loop iterations
    }
}

// ---------------------------------------------------------------------------
// kernel_launch: graph-capturable, allocation-free.
// Inputs: X, neighbors, h1_w, h1_b, g1_w, g1_b, final_w, final_b
// ---------------------------------------------------------------------------
extern "C" void kernel_launch(void* const* d_in, const int* in_sizes, int n_in,
                              void* d_out, int out_size)
{
    const float* X    = (const float*)d_in[0];
    const int*   nbr  = (const int*)  d_in[1];
    const float* h1w  = (const float*)d_in[2];
    const float* h1b  = (const float*)d_in[3];
    const float* g1w  = (const float*)d_in[4];
    const float* g1b  = (const float*)d_in[5];
    const float* fw   = (const float*)d_in[6];
    const float* fb   = (const float*)d_in[7];
    float* out = (float*)d_out;

    (void)in_sizes; (void)n_in; (void)out_size;

    prep_kernel<<<296, 256>>>(X, h1w, h1b, g1w);
    ggcn_main_kernel<<<148, 256>>>(nbr, g1w, g1b, fw, fb, out);
}